// round 2
// baseline (speedup 1.0000x reference)
#include <cuda_runtime.h>

#define P_DIM 512
#define Q_DIM 64
#define B_DIM 16
#define E_DIM 256
#define H_DIM 256
#define O_DIM 256

// ---------------- scratch (static __device__, no allocation) ----------------
__device__ float g_Wp[P_DIM * B_DIM * H_DIM];          // (P,B,H)
__device__ float g_Wq[Q_DIM * B_DIM * H_DIM];          // (Q,B,H)
__device__ float g_gcat[P_DIM * B_DIM * 2 * E_DIM];    // (P,B,2E) = [passage | c]
__device__ float g_cg[P_DIM * B_DIM * E_DIM];          // c_gated
__device__ float g_gi[P_DIM * B_DIM * 3 * O_DIM];      // gi = x@w_ih^T + b_ih

// ---------------- math helpers ----------------
__device__ __forceinline__ float fast_tanh(float x) {
    float e = __expf(2.f * x);
    return 1.f - __fdividef(2.f, e + 1.f);
}
__device__ __forceinline__ float fast_sigmoid(float x) {
    return __fdividef(1.f, 1.f + __expf(-x));
}
__device__ __forceinline__ unsigned smem_u32(const void* p) {
    return (unsigned)__cvta_generic_to_shared(p);
}
__device__ __forceinline__ void fma_f32x2(unsigned long long& acc,
                                          unsigned long long a,
                                          unsigned long long b) {
    asm("fma.rn.f32x2 %0, %1, %2, %0;" : "+l"(acc) : "l"(a), "l"(b));
}

// ---------------- generic fp32 GEMM: C[M,N] = epi(A[M,K] @ W[N,K]^T) ----------------
// MODE 0: raw    MODE 1: + bias[n]    MODE 2: sigmoid(acc) * aux[row*512 + 256 + n]
template <int MODE>
__global__ __launch_bounds__(256) void gemm_kernel(
    const float* __restrict__ A, const float* __restrict__ W,
    const float* __restrict__ bias, const float* __restrict__ aux,
    float* __restrict__ C, int M, int N, int K)
{
    __shared__ float As[32 * 68];   // [k][m], padded stride 68
    __shared__ float Ws[32 * 68];   // [k][n]

    const int tid = threadIdx.x;
    const int m0 = blockIdx.x * 64;
    const int n0 = blockIdx.y * 64;
    const int tm = tid >> 4;   // 0..15
    const int tn = tid & 15;   // 0..15
    const int K4 = K >> 2;

    float acc[4][4];
#pragma unroll
    for (int i = 0; i < 4; i++)
#pragma unroll
        for (int j = 0; j < 4; j++) acc[i][j] = 0.f;

    const float4* A4 = (const float4*)A;
    const float4* W4 = (const float4*)W;

    for (int k0 = 0; k0 < K; k0 += 32) {
#pragma unroll
        for (int t = 0; t < 2; t++) {
            int idx = tid + t * 256;          // 0..511
            int r = idx >> 3;                 // 0..63
            int c4 = idx & 7;                 // 0..7
            float4 va = A4[(long)(m0 + r) * K4 + (k0 >> 2) + c4];
            float4 vw = W4[(long)(n0 + r) * K4 + (k0 >> 2) + c4];
            int kk = c4 * 4;
            As[(kk + 0) * 68 + r] = va.x; As[(kk + 1) * 68 + r] = va.y;
            As[(kk + 2) * 68 + r] = va.z; As[(kk + 3) * 68 + r] = va.w;
            Ws[(kk + 0) * 68 + r] = vw.x; Ws[(kk + 1) * 68 + r] = vw.y;
            Ws[(kk + 2) * 68 + r] = vw.z; Ws[(kk + 3) * 68 + r] = vw.w;
        }
        __syncthreads();

        const float4* As4 = (const float4*)As;
        const float4* Ws4 = (const float4*)Ws;
#pragma unroll
        for (int k = 0; k < 32; k++) {
            float4 a = As4[k * 17 + tm];
            float4 w = Ws4[k * 17 + tn];
            acc[0][0] += a.x * w.x; acc[0][1] += a.x * w.y; acc[0][2] += a.x * w.z; acc[0][3] += a.x * w.w;
            acc[1][0] += a.y * w.x; acc[1][1] += a.y * w.y; acc[1][2] += a.y * w.z; acc[1][3] += a.y * w.w;
            acc[2][0] += a.z * w.x; acc[2][1] += a.z * w.y; acc[2][2] += a.z * w.z; acc[2][3] += a.z * w.w;
            acc[3][0] += a.w * w.x; acc[3][1] += a.w * w.y; acc[3][2] += a.w * w.z; acc[3][3] += a.w * w.w;
        }
        __syncthreads();
    }

#pragma unroll
    for (int i = 0; i < 4; i++) {
        int row = m0 + tm * 4 + i;
        int col = n0 + tn * 4;
        float4 o;
        if (MODE == 0) {
            o = make_float4(acc[i][0], acc[i][1], acc[i][2], acc[i][3]);
        } else if (MODE == 1) {
            o = make_float4(acc[i][0] + bias[col + 0], acc[i][1] + bias[col + 1],
                            acc[i][2] + bias[col + 2], acc[i][3] + bias[col + 3]);
        } else {
            float4 g = *(const float4*)(aux + (long)row * 512 + 256 + col);
            o = make_float4(fast_sigmoid(acc[i][0]) * g.x, fast_sigmoid(acc[i][1]) * g.y,
                            fast_sigmoid(acc[i][2]) * g.z, fast_sigmoid(acc[i][3]) * g.w);
        }
        *(float4*)(&C[(long)row * N + col]) = o;
    }
}

// ---------------- fused attention: scores -> softmax -> context -> concat ----------------
__global__ __launch_bounds__(256) void attn_kernel(
    const float* __restrict__ question, const float* __restrict__ passage,
    const float* __restrict__ v)
{
    __shared__ float wp[256];
    __shared__ float vv[256];
    __shared__ float sc[64];

    const int p = blockIdx.x;
    const int b = blockIdx.y;
    const int tid = threadIdx.x;
    const int w = tid >> 5, l = tid & 31;

    wp[tid] = g_Wp[((long)p * B_DIM + b) * H_DIM + tid];
    vv[tid] = v[tid];
    __syncthreads();

#pragma unroll
    for (int qi = 0; qi < 8; qi++) {
        int q = w * 8 + qi;
        const float* wq = &g_Wq[((long)q * B_DIM + b) * H_DIM];
        float acc = 0.f;
#pragma unroll
        for (int j = 0; j < 8; j++) {
            int h = l + 32 * j;
            acc += vv[h] * fast_tanh(wq[h] + wp[h]);
        }
#pragma unroll
        for (int s = 16; s > 0; s >>= 1) acc += __shfl_xor_sync(0xffffffffu, acc, s);
        if (l == 0) sc[q] = acc;
    }
    __syncthreads();

    if (w == 0) {
        float s0 = sc[l], s1 = sc[32 + l];
        float m = fmaxf(s0, s1);
#pragma unroll
        for (int s = 16; s > 0; s >>= 1) m = fmaxf(m, __shfl_xor_sync(0xffffffffu, m, s));
        float e0 = __expf(s0 - m), e1 = __expf(s1 - m);
        float sum = e0 + e1;
#pragma unroll
        for (int s = 16; s > 0; s >>= 1) sum += __shfl_xor_sync(0xffffffffu, sum, s);
        float inv = __fdividef(1.f, sum);
        sc[l] = e0 * inv;
        sc[32 + l] = e1 * inv;
    }
    __syncthreads();

    float acc = 0.f;
#pragma unroll
    for (int q = 0; q < 64; q++)
        acc += sc[q] * question[((long)q * B_DIM + b) * E_DIM + tid];

    float* gr = &g_gcat[((long)p * B_DIM + b) * 2 * E_DIM];
    gr[256 + tid] = acc;
    gr[tid] = passage[((long)p * B_DIM + b) * E_DIM + tid];
}

// ---------------- GRU v2: 8-CTA cluster / batch, mbarrier handshake, f32x2 FMA ------
// Per-CTA: 96 gate rows (r/z/n for 32 outputs), w_hh slice in registers (packed f32x2).
// Per step: DSMEM-broadcast 32 h values to all 8 CTAs + 1 release-arrive per peer;
// consumers try_wait.parity.acquire.cluster (no full cluster barrier, no L1 flush).
__global__ void __cluster_dims__(8, 1, 1) __launch_bounds__(384, 1)
gru_kernel(const float* __restrict__ gi, const float* __restrict__ w_hh,
           const float* __restrict__ b_hh, float* __restrict__ out)
{
    __shared__ __align__(16) float hb[2][4 * 68];   // h double buffer, slot (o>>6)*68+(o&63)
    __shared__ float ghs[96];
    __shared__ float bhh_s[96];
    __shared__ __align__(8) unsigned long long mb[2];

    const int tid = threadIdx.x;
    const int b = blockIdx.x >> 3;     // batch
    const int rank = blockIdx.x & 7;   // cluster rank
    const int rloc = tid >> 2;         // local row 0..95
    const int q = tid & 3;             // K-slice 0..3 (64 floats each)
    const int gate = rloc >> 5;        // 0=r,1=z,2=n
    const int oc = rloc & 31;
    const int grow = gate * 256 + rank * 32 + oc;   // global w_hh row

    // preload + pack 64 weights as 32 f32x2 operands
    unsigned long long w01[16], w23[16];
    {
        const float4* wg4 = (const float4*)(w_hh + (long)grow * 256 + q * 64);
#pragma unroll
        for (int i = 0; i < 16; i++) {
            float4 t = wg4[i];
            asm("mov.b64 %0, {%1,%2};" : "=l"(w01[i]) : "f"(t.x), "f"(t.y));
            asm("mov.b64 %0, {%1,%2};" : "=l"(w23[i]) : "f"(t.z), "f"(t.w));
        }
    }

    if (tid < 96) bhh_s[tid] = b_hh[(tid >> 5) * 256 + rank * 32 + (tid & 31)];
    for (int i = tid; i < 2 * 4 * 68; i += 384) ((float*)hb)[i] = 0.f;
    if (tid == 0) {
        asm volatile("mbarrier.init.shared.b64 [%0], %1;" :: "r"(smem_u32(&mb[0])), "r"(8) : "memory");
        asm volatile("mbarrier.init.shared.b64 [%0], %1;" :: "r"(smem_u32(&mb[1])), "r"(8) : "memory");
    }
    __syncthreads();
    // all CTAs' barriers + h buffers initialized before any remote traffic
    asm volatile("barrier.cluster.arrive.aligned;" ::: "memory");
    asm volatile("barrier.cluster.wait.aligned;" ::: "memory");

    const unsigned mb0 = smem_u32(&mb[0]);
    const unsigned mb1 = smem_u32(&mb[1]);

    for (int p = 0; p < P_DIM; p++) {
        const int cur = p & 1;
        const int nxt = cur ^ 1;

        // prefetch gi for this step (global loads overlap the wait below)
        float gir = 0.f, giz = 0.f, gin = 0.f;
        if (tid < 32) {
            long base = ((long)p * B_DIM + b) * 768 + rank * 32 + tid;
            gir = gi[base];
            giz = gi[base + 256];
            gin = gi[base + 512];
        }

        // wait for hb[cur] to be fully delivered by all 8 CTAs (skip p==0: h=0 preset)
        if (p > 0) {
            unsigned mba = cur ? mb1 : mb0;
            int ph = ((p - 2 + (p & 1)) >> 1) & 1;
            asm volatile(
                "{\n\t.reg .pred P1;\n\t"
                "WL_%=:\n\t"
                "mbarrier.try_wait.parity.acquire.cluster.shared::cta.b64 P1, [%0], %1, 0x989680;\n\t"
                "@P1 bra.uni WD_%=;\n\t"
                "bra.uni WL_%=;\n\t"
                "WD_%=:\n\t}"
                :: "r"(mba), "r"(ph) : "memory");
        }

        // gh[row] = sum_k h[k] * w_hh[row][k]  via packed f32x2 FMA
        const ulonglong2* h2 = (const ulonglong2*)hb[cur];
        unsigned long long a01 = 0ull, a23 = 0ull;   // (0.f,0.f) pairs
#pragma unroll
        for (int i = 0; i < 16; i++) {
            ulonglong2 hv = h2[q * 17 + i];
            fma_f32x2(a01, w01[i], hv.x);
            fma_f32x2(a23, w23[i], hv.y);
        }
        unsigned long long s2;
        asm("add.rn.f32x2 %0, %1, %2;" : "=l"(s2) : "l"(a01), "l"(a23));
        float lo, hi;
        asm("mov.b64 {%0,%1}, %2;" : "=f"(lo), "=f"(hi) : "l"(s2));
        float acc = lo + hi;
        acc += __shfl_xor_sync(0xffffffffu, acc, 1);
        acc += __shfl_xor_sync(0xffffffffu, acc, 2);
        if (q == 0) ghs[rloc] = acc;
        __syncthreads();

        if (tid < 32) {   // warp 0: gates + output + broadcast
            int o = rank * 32 + tid;
            float ghr = ghs[tid]      + bhh_s[tid];
            float ghz = ghs[32 + tid] + bhh_s[32 + tid];
            float ghn = ghs[64 + tid] + bhh_s[64 + tid];
            float r = fast_sigmoid(gir + ghr);
            float z = fast_sigmoid(giz + ghz);
            float n = fast_tanh(gin + r * ghn);
            float hold = hb[cur][(o >> 6) * 68 + (o & 63)];
            float hnew = (1.f - z) * n + z * hold;
            out[((long)p * B_DIM + b) * O_DIM + o] = hnew;

            if (p < P_DIM - 1) {
                // broadcast h_new element to hb[nxt] of every CTA in the cluster
                unsigned laddr = smem_u32(&hb[nxt][(o >> 6) * 68 + (o & 63)]);
#pragma unroll
                for (int c2 = 0; c2 < 8; c2++) {
                    unsigned raddr;
                    asm("mapa.shared::cluster.u32 %0, %1, %2;" : "=r"(raddr) : "r"(laddr), "r"(c2));
                    asm volatile("st.shared::cluster.f32 [%0], %1;" :: "r"(raddr), "f"(hnew));
                }
                __syncwarp();
                if (tid == 0) {
                    // one release-arrive per peer: orders this warp's DSMEM stores
                    unsigned lmb = nxt ? mb1 : mb0;
#pragma unroll
                    for (int c2 = 0; c2 < 8; c2++) {
                        unsigned rmb;
                        asm("mapa.shared::cluster.u32 %0, %1, %2;" : "=r"(rmb) : "r"(lmb), "r"(c2));
                        asm volatile("mbarrier.arrive.release.cluster.shared::cluster.b64 _, [%0];"
                                     :: "r"(rmb) : "memory");
                    }
                }
            }
        }
    }
}

// ---------------- launch ----------------
extern "C" void kernel_launch(void* const* d_in, const int* in_sizes, int n_in,
                              void* d_out, int out_size)
{
    const float* passage  = (const float*)d_in[0];
    const float* question = (const float*)d_in[1];
    const float* Wuq      = (const float*)d_in[2];
    const float* Wup      = (const float*)d_in[3];
    const float* v        = (const float*)d_in[4];
    const float* Wg       = (const float*)d_in[5];
    const float* w_ih     = (const float*)d_in[6];
    const float* w_hh     = (const float*)d_in[7];
    const float* b_ih     = (const float*)d_in[8];
    const float* b_hh     = (const float*)d_in[9];
    float* out = (float*)d_out;

    void *pWp, *pWq, *pGcat, *pCg, *pGi;
    cudaGetSymbolAddress(&pWp, g_Wp);
    cudaGetSymbolAddress(&pWq, g_Wq);
    cudaGetSymbolAddress(&pGcat, g_gcat);
    cudaGetSymbolAddress(&pCg, g_cg);
    cudaGetSymbolAddress(&pGi, g_gi);

    dim3 blk(256);

    gemm_kernel<0><<<dim3(8192 / 64, 256 / 64), blk>>>(
        passage, Wup, nullptr, nullptr, (float*)pWp, 8192, 256, 256);
    gemm_kernel<0><<<dim3(1024 / 64, 256 / 64), blk>>>(
        question, Wuq, nullptr, nullptr, (float*)pWq, 1024, 256, 256);
    attn_kernel<<<dim3(P_DIM, B_DIM), blk>>>(question, passage, v);
    gemm_kernel<2><<<dim3(8192 / 64, 256 / 64), blk>>>(
        (const float*)pGcat, Wg + 256 * 512, nullptr, (const float*)pGcat,
        (float*)pCg, 8192, 256, 512);
    gemm_kernel<1><<<dim3(8192 / 64, 768 / 64), blk>>>(
        (const float*)pCg, w_ih, b_ih, nullptr, (float*)pGi, 8192, 768, 256);
    gru_kernel<<<128, 384>>>((const float*)pGi, w_hh, b_hh, out);
}

// round 3
// speedup vs baseline: 1.4884x; 1.4884x over previous
#include <cuda_runtime.h>

#define P_DIM 512
#define Q_DIM 64
#define B_DIM 16
#define E_DIM 256
#define H_DIM 256
#define O_DIM 256

// ---------------- scratch (static __device__, no allocation) ----------------
__device__ float g_Wp[P_DIM * B_DIM * H_DIM];          // (P,B,H)
__device__ float g_Wq[Q_DIM * B_DIM * H_DIM];          // (Q,B,H)
__device__ float g_gcat[P_DIM * B_DIM * 2 * E_DIM];    // (P,B,2E) = [passage | c]
__device__ float g_cg[P_DIM * B_DIM * E_DIM];          // c_gated
__device__ float g_gi[P_DIM * B_DIM * 3 * O_DIM];      // gi = x@w_ih^T + b_ih

// ---------------- math helpers ----------------
__device__ __forceinline__ float fast_tanh(float x) {
    float e = __expf(2.f * x);
    return 1.f - __fdividef(2.f, e + 1.f);
}
__device__ __forceinline__ float fast_sigmoid(float x) {
    return __fdividef(1.f, 1.f + __expf(-x));
}
__device__ __forceinline__ unsigned smem_u32(const void* p) {
    return (unsigned)__cvta_generic_to_shared(p);
}
__device__ __forceinline__ void fma_f32x2(unsigned long long& acc,
                                          unsigned long long a,
                                          unsigned long long b) {
    asm("fma.rn.f32x2 %0, %1, %2, %0;" : "+l"(acc) : "l"(a), "l"(b));
}

// ---------------- generic fp32 GEMM: C[M,N] = epi(A[M,K] @ W[N,K]^T) ----------------
// MODE 0: raw    MODE 1: + bias[n]    MODE 2: sigmoid(acc) * aux[row*512 + 256 + n]
template <int MODE>
__global__ __launch_bounds__(256) void gemm_kernel(
    const float* __restrict__ A, const float* __restrict__ W,
    const float* __restrict__ bias, const float* __restrict__ aux,
    float* __restrict__ C, int M, int N, int K)
{
    __shared__ float As[32 * 68];   // [k][m], padded stride 68
    __shared__ float Ws[32 * 68];   // [k][n]

    const int tid = threadIdx.x;
    const int m0 = blockIdx.x * 64;
    const int n0 = blockIdx.y * 64;
    const int tm = tid >> 4;   // 0..15
    const int tn = tid & 15;   // 0..15
    const int K4 = K >> 2;

    float acc[4][4];
#pragma unroll
    for (int i = 0; i < 4; i++)
#pragma unroll
        for (int j = 0; j < 4; j++) acc[i][j] = 0.f;

    const float4* A4 = (const float4*)A;
    const float4* W4 = (const float4*)W;

    for (int k0 = 0; k0 < K; k0 += 32) {
#pragma unroll
        for (int t = 0; t < 2; t++) {
            int idx = tid + t * 256;          // 0..511
            int r = idx >> 3;                 // 0..63
            int c4 = idx & 7;                 // 0..7
            float4 va = A4[(long)(m0 + r) * K4 + (k0 >> 2) + c4];
            float4 vw = W4[(long)(n0 + r) * K4 + (k0 >> 2) + c4];
            int kk = c4 * 4;
            As[(kk + 0) * 68 + r] = va.x; As[(kk + 1) * 68 + r] = va.y;
            As[(kk + 2) * 68 + r] = va.z; As[(kk + 3) * 68 + r] = va.w;
            Ws[(kk + 0) * 68 + r] = vw.x; Ws[(kk + 1) * 68 + r] = vw.y;
            Ws[(kk + 2) * 68 + r] = vw.z; Ws[(kk + 3) * 68 + r] = vw.w;
        }
        __syncthreads();

        const float4* As4 = (const float4*)As;
        const float4* Ws4 = (const float4*)Ws;
#pragma unroll
        for (int k = 0; k < 32; k++) {
            float4 a = As4[k * 17 + tm];
            float4 w = Ws4[k * 17 + tn];
            acc[0][0] += a.x * w.x; acc[0][1] += a.x * w.y; acc[0][2] += a.x * w.z; acc[0][3] += a.x * w.w;
            acc[1][0] += a.y * w.x; acc[1][1] += a.y * w.y; acc[1][2] += a.y * w.z; acc[1][3] += a.y * w.w;
            acc[2][0] += a.z * w.x; acc[2][1] += a.z * w.y; acc[2][2] += a.z * w.z; acc[2][3] += a.z * w.w;
            acc[3][0] += a.w * w.x; acc[3][1] += a.w * w.y; acc[3][2] += a.w * w.z; acc[3][3] += a.w * w.w;
        }
        __syncthreads();
    }

#pragma unroll
    for (int i = 0; i < 4; i++) {
        int row = m0 + tm * 4 + i;
        int col = n0 + tn * 4;
        float4 o;
        if (MODE == 0) {
            o = make_float4(acc[i][0], acc[i][1], acc[i][2], acc[i][3]);
        } else if (MODE == 1) {
            o = make_float4(acc[i][0] + bias[col + 0], acc[i][1] + bias[col + 1],
                            acc[i][2] + bias[col + 2], acc[i][3] + bias[col + 3]);
        } else {
            float4 g = *(const float4*)(aux + (long)row * 512 + 256 + col);
            o = make_float4(fast_sigmoid(acc[i][0]) * g.x, fast_sigmoid(acc[i][1]) * g.y,
                            fast_sigmoid(acc[i][2]) * g.z, fast_sigmoid(acc[i][3]) * g.w);
        }
        *(float4*)(&C[(long)row * N + col]) = o;
    }
}

// ---------------- fused attention: scores -> softmax -> context -> concat ----------------
__global__ __launch_bounds__(256) void attn_kernel(
    const float* __restrict__ question, const float* __restrict__ passage,
    const float* __restrict__ v)
{
    __shared__ float wp[256];
    __shared__ float vv[256];
    __shared__ float sc[64];

    const int p = blockIdx.x;
    const int b = blockIdx.y;
    const int tid = threadIdx.x;
    const int w = tid >> 5, l = tid & 31;

    wp[tid] = g_Wp[((long)p * B_DIM + b) * H_DIM + tid];
    vv[tid] = v[tid];
    __syncthreads();

#pragma unroll
    for (int qi = 0; qi < 8; qi++) {
        int q = w * 8 + qi;
        const float* wq = &g_Wq[((long)q * B_DIM + b) * H_DIM];
        float acc = 0.f;
#pragma unroll
        for (int j = 0; j < 8; j++) {
            int h = l + 32 * j;
            acc += vv[h] * fast_tanh(wq[h] + wp[h]);
        }
#pragma unroll
        for (int s = 16; s > 0; s >>= 1) acc += __shfl_xor_sync(0xffffffffu, acc, s);
        if (l == 0) sc[q] = acc;
    }
    __syncthreads();

    if (w == 0) {
        float s0 = sc[l], s1 = sc[32 + l];
        float m = fmaxf(s0, s1);
#pragma unroll
        for (int s = 16; s > 0; s >>= 1) m = fmaxf(m, __shfl_xor_sync(0xffffffffu, m, s));
        float e0 = __expf(s0 - m), e1 = __expf(s1 - m);
        float sum = e0 + e1;
#pragma unroll
        for (int s = 16; s > 0; s >>= 1) sum += __shfl_xor_sync(0xffffffffu, sum, s);
        float inv = __fdividef(1.f, sum);
        sc[l] = e0 * inv;
        sc[32 + l] = e1 * inv;
    }
    __syncthreads();

    float acc = 0.f;
#pragma unroll
    for (int q = 0; q < 64; q++)
        acc += sc[q] * question[((long)q * B_DIM + b) * E_DIM + tid];

    float* gr = &g_gcat[((long)p * B_DIM + b) * 2 * E_DIM];
    gr[256 + tid] = acc;
    gr[tid] = passage[((long)p * B_DIM + b) * E_DIM + tid];
}

// ---------------- GRU v3: 8-CTA cluster / batch, local-smem flag handshake ----------
// Per step, warp 0 of each CTA: DSMEM-stores its 32 h values to all 8 CTAs'
// hb[nxt], one warp-wide fence.acq_rel.cluster, then lanes 0-7 store a monotone
// step counter into each peer's flags[nxt][myrank]. Consumers spin on LOCAL
// smem flags (no fabric traffic while polling), then fence once.
__global__ void __cluster_dims__(8, 1, 1) __launch_bounds__(384, 1)
gru_kernel(const float* __restrict__ gi, const float* __restrict__ w_hh,
           const float* __restrict__ b_hh, float* __restrict__ out)
{
    __shared__ __align__(16) float hb[2][4 * 68];   // h double buffer, slot (o>>6)*68+(o&63)
    __shared__ float ghs[96];
    __shared__ float bhh_s[96];
    __shared__ __align__(16) unsigned flags[2][8];  // flags[buf][srcRank] = step counter

    const int tid = threadIdx.x;
    const int lane = tid & 31;
    const int b = blockIdx.x >> 3;     // batch
    const int rank = blockIdx.x & 7;   // cluster rank
    const int rloc = tid >> 2;         // local row 0..95
    const int q = tid & 3;             // K-slice 0..3 (64 floats each)
    const int gate = rloc >> 5;        // 0=r,1=z,2=n
    const int oc = rloc & 31;
    const int grow = gate * 256 + rank * 32 + oc;   // global w_hh row

    // preload + pack 64 weights as 32 f32x2 operands
    unsigned long long w01[16], w23[16];
    {
        const float4* wg4 = (const float4*)(w_hh + (long)grow * 256 + q * 64);
#pragma unroll
        for (int i = 0; i < 16; i++) {
            float4 t = wg4[i];
            asm("mov.b64 %0, {%1,%2};" : "=l"(w01[i]) : "f"(t.x), "f"(t.y));
            asm("mov.b64 %0, {%1,%2};" : "=l"(w23[i]) : "f"(t.z), "f"(t.w));
        }
    }

    if (tid < 96) bhh_s[tid] = b_hh[(tid >> 5) * 256 + rank * 32 + (tid & 31)];
    for (int i = tid; i < 2 * 4 * 68; i += 384) ((float*)hb)[i] = 0.f;
    if (tid < 16) ((unsigned*)flags)[tid] = 0u;
    __syncthreads();
    // all CTAs' smem initialized before any remote traffic
    asm volatile("barrier.cluster.arrive.aligned;" ::: "memory");
    asm volatile("barrier.cluster.wait.aligned;" ::: "memory");

    for (int p = 0; p < P_DIM; p++) {
        const int cur = p & 1;
        const int nxt = cur ^ 1;

        // prefetch gi for this step (global loads overlap the wait below)
        float gir = 0.f, giz = 0.f, gin = 0.f;
        if (tid < 32) {
            long base = ((long)p * B_DIM + b) * 768 + rank * 32 + tid;
            gir = gi[base];
            giz = gi[base + 256];
            gin = gi[base + 512];
        }

        // wait: all 8 source flags for hb[cur] must reach p (skip p==0: h preset to 0)
        if (p > 0) {
            const unsigned fa = smem_u32(&flags[cur][lane & 7]);
            const unsigned target = (unsigned)p;
            for (;;) {
                unsigned f;
                asm volatile("ld.volatile.shared.u32 %0, [%1];" : "=r"(f) : "r"(fa));
                unsigned ok = (lane < 8) ? (f >= target) : 1u;
                if (__ballot_sync(0xffffffffu, ok) == 0xffffffffu) break;
            }
            asm volatile("fence.acq_rel.cluster;" ::: "memory");
        }

        // gh[row] = sum_k h[k] * w_hh[row][k]  via packed f32x2 FMA
        const ulonglong2* h2 = (const ulonglong2*)hb[cur];
        unsigned long long a01 = 0ull, a23 = 0ull;
#pragma unroll
        for (int i = 0; i < 16; i++) {
            ulonglong2 hv = h2[q * 17 + i];
            fma_f32x2(a01, w01[i], hv.x);
            fma_f32x2(a23, w23[i], hv.y);
        }
        unsigned long long s2;
        asm("add.rn.f32x2 %0, %1, %2;" : "=l"(s2) : "l"(a01), "l"(a23));
        float lo, hi;
        asm("mov.b64 {%0,%1}, %2;" : "=f"(lo), "=f"(hi) : "l"(s2));
        float acc = lo + hi;
        acc += __shfl_xor_sync(0xffffffffu, acc, 1);
        acc += __shfl_xor_sync(0xffffffffu, acc, 2);
        if (q == 0) ghs[rloc] = acc;
        __syncthreads();

        if (tid < 32) {   // warp 0: gates + output + broadcast + flags
            int o = rank * 32 + tid;
            float ghr = ghs[tid]      + bhh_s[tid];
            float ghz = ghs[32 + tid] + bhh_s[32 + tid];
            float ghn = ghs[64 + tid] + bhh_s[64 + tid];
            float r = fast_sigmoid(gir + ghr);
            float z = fast_sigmoid(giz + ghz);
            float n = fast_tanh(gin + r * ghn);
            float hold = hb[cur][(o >> 6) * 68 + (o & 63)];
            float hnew = (1.f - z) * n + z * hold;
            out[((long)p * B_DIM + b) * O_DIM + o] = hnew;

            if (p < P_DIM - 1) {
                // broadcast h_new element to hb[nxt] of every CTA (fire-and-forget)
                unsigned laddr = smem_u32(&hb[nxt][(o >> 6) * 68 + (o & 63)]);
#pragma unroll
                for (int c2 = 0; c2 < 8; c2++) {
                    unsigned raddr;
                    asm("mapa.shared::cluster.u32 %0, %1, %2;" : "=r"(raddr) : "r"(laddr), "r"(c2));
                    asm volatile("st.shared::cluster.f32 [%0], %1;" :: "r"(raddr), "f"(hnew));
                }
                __syncwarp();
                // one warp-wide fence orders the warp's stores; lanes 0-7 then
                // publish the step counter to each peer's flags[nxt][rank].
                asm volatile("fence.acq_rel.cluster;" ::: "memory");
                if (tid < 8) {
                    unsigned lf = smem_u32(&flags[nxt][rank]);
                    unsigned rf;
                    asm("mapa.shared::cluster.u32 %0, %1, %2;" : "=r"(rf) : "r"(lf), "r"(tid));
                    asm volatile("st.shared::cluster.u32 [%0], %1;" :: "r"(rf), "r"((unsigned)(p + 1)));
                }
            }
        }
    }
}

// ---------------- launch ----------------
extern "C" void kernel_launch(void* const* d_in, const int* in_sizes, int n_in,
                              void* d_out, int out_size)
{
    const float* passage  = (const float*)d_in[0];
    const float* question = (const float*)d_in[1];
    const float* Wuq      = (const float*)d_in[2];
    const float* Wup      = (const float*)d_in[3];
    const float* v        = (const float*)d_in[4];
    const float* Wg       = (const float*)d_in[5];
    const float* w_ih     = (const float*)d_in[6];
    const float* w_hh     = (const float*)d_in[7];
    const float* b_ih     = (const float*)d_in[8];
    const float* b_hh     = (const float*)d_in[9];
    float* out = (float*)d_out;

    void *pWp, *pWq, *pGcat, *pCg, *pGi;
    cudaGetSymbolAddress(&pWp, g_Wp);
    cudaGetSymbolAddress(&pWq, g_Wq);
    cudaGetSymbolAddress(&pGcat, g_gcat);
    cudaGetSymbolAddress(&pCg, g_cg);
    cudaGetSymbolAddress(&pGi, g_gi);

    dim3 blk(256);

    gemm_kernel<0><<<dim3(8192 / 64, 256 / 64), blk>>>(
        passage, Wup, nullptr, nullptr, (float*)pWp, 8192, 256, 256);
    gemm_kernel<0><<<dim3(1024 / 64, 256 / 64), blk>>>(
        question, Wuq, nullptr, nullptr, (float*)pWq, 1024, 256, 256);
    attn_kernel<<<dim3(P_DIM, B_DIM), blk>>>(question, passage, v);
    gemm_kernel<2><<<dim3(8192 / 64, 256 / 64), blk>>>(
        (const float*)pGcat, Wg + 256 * 512, nullptr, (const float*)pGcat,
        (float*)pCg, 8192, 256, 512);
    gemm_kernel<1><<<dim3(8192 / 64, 768 / 64), blk>>>(
        (const float*)pCg, w_ih, b_ih, nullptr, (float*)pGi, 8192, 768, 256);
    gru_kernel<<<128, 384>>>((const float*)pGi, w_hh, b_hh, out);
}

// round 4
// speedup vs baseline: 1.6729x; 1.1239x over previous
#include <cuda_runtime.h>

#define P_DIM 512
#define Q_DIM 64
#define B_DIM 16
#define E_DIM 256
#define H_DIM 256
#define O_DIM 256

// ---------------- scratch (static __device__, no allocation) ----------------
__device__ float g_Wp[P_DIM * B_DIM * H_DIM];          // (P,B,H)
__device__ float g_Wq[Q_DIM * B_DIM * H_DIM];          // (Q,B,H)
__device__ float g_gcat[P_DIM * B_DIM * 2 * E_DIM];    // (P,B,2E) = [passage | c]
__device__ float g_cg[P_DIM * B_DIM * E_DIM];          // c_gated
__device__ float g_gi[P_DIM * B_DIM * 3 * O_DIM];      // gi = x@w_ih^T + b_ih

// ---------------- math helpers ----------------
__device__ __forceinline__ float fast_tanh(float x) {
    float e = __expf(2.f * x);
    return 1.f - __fdividef(2.f, e + 1.f);
}
__device__ __forceinline__ float fast_sigmoid(float x) {
    return __fdividef(1.f, 1.f + __expf(-x));
}
__device__ __forceinline__ unsigned smem_u32(const void* p) {
    return (unsigned)__cvta_generic_to_shared(p);
}
__device__ __forceinline__ void fma_f32x2(unsigned long long& acc,
                                          unsigned long long a,
                                          unsigned long long b) {
    asm("fma.rn.f32x2 %0, %1, %2, %0;" : "+l"(acc) : "l"(a), "l"(b));
}

// ---------------- generic fp32 GEMM: C[M,N] = epi(A[M,K] @ W[N,K]^T) ----------------
// MODE 0: raw    MODE 1: + bias[n]    MODE 2: sigmoid(acc) * aux[row*512 + 256 + n]
template <int MODE>
__global__ __launch_bounds__(256) void gemm_kernel(
    const float* __restrict__ A, const float* __restrict__ W,
    const float* __restrict__ bias, const float* __restrict__ aux,
    float* __restrict__ C, int M, int N, int K)
{
    __shared__ float As[32 * 68];   // [k][m], padded stride 68
    __shared__ float Ws[32 * 68];   // [k][n]

    const int tid = threadIdx.x;
    const int m0 = blockIdx.x * 64;
    const int n0 = blockIdx.y * 64;
    const int tm = tid >> 4;   // 0..15
    const int tn = tid & 15;   // 0..15
    const int K4 = K >> 2;

    float acc[4][4];
#pragma unroll
    for (int i = 0; i < 4; i++)
#pragma unroll
        for (int j = 0; j < 4; j++) acc[i][j] = 0.f;

    const float4* A4 = (const float4*)A;
    const float4* W4 = (const float4*)W;

    for (int k0 = 0; k0 < K; k0 += 32) {
#pragma unroll
        for (int t = 0; t < 2; t++) {
            int idx = tid + t * 256;          // 0..511
            int r = idx >> 3;                 // 0..63
            int c4 = idx & 7;                 // 0..7
            float4 va = A4[(long)(m0 + r) * K4 + (k0 >> 2) + c4];
            float4 vw = W4[(long)(n0 + r) * K4 + (k0 >> 2) + c4];
            int kk = c4 * 4;
            As[(kk + 0) * 68 + r] = va.x; As[(kk + 1) * 68 + r] = va.y;
            As[(kk + 2) * 68 + r] = va.z; As[(kk + 3) * 68 + r] = va.w;
            Ws[(kk + 0) * 68 + r] = vw.x; Ws[(kk + 1) * 68 + r] = vw.y;
            Ws[(kk + 2) * 68 + r] = vw.z; Ws[(kk + 3) * 68 + r] = vw.w;
        }
        __syncthreads();

        const float4* As4 = (const float4*)As;
        const float4* Ws4 = (const float4*)Ws;
#pragma unroll
        for (int k = 0; k < 32; k++) {
            float4 a = As4[k * 17 + tm];
            float4 w = Ws4[k * 17 + tn];
            acc[0][0] += a.x * w.x; acc[0][1] += a.x * w.y; acc[0][2] += a.x * w.z; acc[0][3] += a.x * w.w;
            acc[1][0] += a.y * w.x; acc[1][1] += a.y * w.y; acc[1][2] += a.y * w.z; acc[1][3] += a.y * w.w;
            acc[2][0] += a.z * w.x; acc[2][1] += a.z * w.y; acc[2][2] += a.z * w.z; acc[2][3] += a.z * w.w;
            acc[3][0] += a.w * w.x; acc[3][1] += a.w * w.y; acc[3][2] += a.w * w.z; acc[3][3] += a.w * w.w;
        }
        __syncthreads();
    }

#pragma unroll
    for (int i = 0; i < 4; i++) {
        int row = m0 + tm * 4 + i;
        int col = n0 + tn * 4;
        float4 o;
        if (MODE == 0) {
            o = make_float4(acc[i][0], acc[i][1], acc[i][2], acc[i][3]);
        } else if (MODE == 1) {
            o = make_float4(acc[i][0] + bias[col + 0], acc[i][1] + bias[col + 1],
                            acc[i][2] + bias[col + 2], acc[i][3] + bias[col + 3]);
        } else {
            float4 g = *(const float4*)(aux + (long)row * 512 + 256 + col);
            o = make_float4(fast_sigmoid(acc[i][0]) * g.x, fast_sigmoid(acc[i][1]) * g.y,
                            fast_sigmoid(acc[i][2]) * g.z, fast_sigmoid(acc[i][3]) * g.w);
        }
        *(float4*)(&C[(long)row * N + col]) = o;
    }
}

// ---------------- fused attention: scores -> softmax -> context -> concat ----------------
__global__ __launch_bounds__(256) void attn_kernel(
    const float* __restrict__ question, const float* __restrict__ passage,
    const float* __restrict__ v)
{
    __shared__ float wp[256];
    __shared__ float vv[256];
    __shared__ float sc[64];

    const int p = blockIdx.x;
    const int b = blockIdx.y;
    const int tid = threadIdx.x;
    const int w = tid >> 5, l = tid & 31;

    wp[tid] = g_Wp[((long)p * B_DIM + b) * H_DIM + tid];
    vv[tid] = v[tid];
    __syncthreads();

#pragma unroll
    for (int qi = 0; qi < 8; qi++) {
        int q = w * 8 + qi;
        const float* wq = &g_Wq[((long)q * B_DIM + b) * H_DIM];
        float acc = 0.f;
#pragma unroll
        for (int j = 0; j < 8; j++) {
            int h = l + 32 * j;
            acc += vv[h] * fast_tanh(wq[h] + wp[h]);
        }
#pragma unroll
        for (int s = 16; s > 0; s >>= 1) acc += __shfl_xor_sync(0xffffffffu, acc, s);
        if (l == 0) sc[q] = acc;
    }
    __syncthreads();

    if (w == 0) {
        float s0 = sc[l], s1 = sc[32 + l];
        float m = fmaxf(s0, s1);
#pragma unroll
        for (int s = 16; s > 0; s >>= 1) m = fmaxf(m, __shfl_xor_sync(0xffffffffu, m, s));
        float e0 = __expf(s0 - m), e1 = __expf(s1 - m);
        float sum = e0 + e1;
#pragma unroll
        for (int s = 16; s > 0; s >>= 1) sum += __shfl_xor_sync(0xffffffffu, sum, s);
        float inv = __fdividef(1.f, sum);
        sc[l] = e0 * inv;
        sc[32 + l] = e1 * inv;
    }
    __syncthreads();

    float acc = 0.f;
#pragma unroll
    for (int q = 0; q < 64; q++)
        acc += sc[q] * question[((long)q * B_DIM + b) * E_DIM + tid];

    float* gr = &g_gcat[((long)p * B_DIM + b) * 2 * E_DIM];
    gr[256 + tid] = acc;
    gr[tid] = passage[((long)p * B_DIM + b) * E_DIM + tid];
}

// ---------------- GRU v4: fence-free self-validating DSMEM protocol ---------------
// h elements travel as 64-bit (counter<<32 | f32bits) relaxed cluster stores.
// A consumer that sees counter==p atomically owns the matching value; counters
// are monotone, so a chunk is fresh iff its counter-sum == 16*p. NO fence,
// NO cluster barrier, NO mbarrier inside the 512-step loop -> no L1 flushes.
__global__ void __cluster_dims__(8, 1, 1) __launch_bounds__(384, 1)
gru_kernel(const float* __restrict__ gi, const float* __restrict__ w_hh,
           const float* __restrict__ b_hh, float* __restrict__ out)
{
    // hb64[buf][slice q (0..3)][66 u64]: 64 elements + 2 pad (528B stride -> conflict-free)
    __shared__ __align__(16) unsigned long long hb64[2][4 * 66];
    __shared__ float ghs[96];
    __shared__ float bhh_s[96];

    const int tid = threadIdx.x;
    const int b = blockIdx.x >> 3;     // batch
    const int rank = blockIdx.x & 7;   // cluster rank
    const int rloc = tid >> 2;         // local row 0..95
    const int q = tid & 3;             // K-slice 0..3 (64 floats each)
    const int gate = rloc >> 5;        // 0=r,1=z,2=n
    const int oc = rloc & 31;
    const int grow = gate * 256 + rank * 32 + oc;   // global w_hh row

    // preload + pack this thread's 64 weights as 32 f32x2 operands
    // wp2[m] pairs with h elements (q*64 + 2m, q*64 + 2m + 1)
    unsigned long long wp2[32];
    {
        const float4* wg4 = (const float4*)(w_hh + (long)grow * 256 + q * 64);
#pragma unroll
        for (int i = 0; i < 16; i++) {
            float4 t = wg4[i];
            asm("mov.b64 %0, {%1,%2};" : "=l"(wp2[2 * i])     : "f"(t.x), "f"(t.y));
            asm("mov.b64 %0, {%1,%2};" : "=l"(wp2[2 * i + 1]) : "f"(t.z), "f"(t.w));
        }
    }

    if (tid < 96) bhh_s[tid] = b_hh[(tid >> 5) * 256 + rank * 32 + (tid & 31)];
    for (int i = tid; i < 2 * 4 * 66; i += 384) ((unsigned long long*)hb64)[i] = 0ull;
    __syncthreads();
    // one-time: all CTAs' smem zeroed before any remote traffic
    asm volatile("barrier.cluster.arrive.aligned;" ::: "memory");
    asm volatile("barrier.cluster.wait.aligned;" ::: "memory");

    const unsigned hbBase0 = smem_u32(&hb64[0][0]);
    const unsigned hbBase1 = smem_u32(&hb64[1][0]);

    for (int p = 0; p < P_DIM; p++) {
        const int cur = p & 1;
        const int nxt = cur ^ 1;

        // prefetch gi for this step (global loads overlap the poll below)
        float gir = 0.f, giz = 0.f, gin = 0.f;
        if (tid < 32) {
            long base = ((long)p * B_DIM + b) * 768 + rank * 32 + tid;
            gir = gi[base];
            giz = gi[base + 256];
            gin = gi[base + 512];
        }

        // gh[row] = sum_k h[k]*w[row][k], chunked: validate 16 elements, then FMA them
        const unsigned hbase = (cur ? hbBase1 : hbBase0) + (unsigned)(q * 528);
        const unsigned tgt = 16u * (unsigned)p;   // counter-sum target per chunk
        unsigned long long acc2 = 0ull;
#pragma unroll
        for (int c = 0; c < 4; c++) {
            unsigned long long hx[8], hy[8];
            for (;;) {
                unsigned s = 0;
#pragma unroll
                for (int i = 0; i < 8; i++) {
                    unsigned a = hbase + (unsigned)((c * 8 + i) * 16);
                    asm volatile("ld.volatile.shared.v2.u64 {%0,%1}, [%2];"
                                 : "=l"(hx[i]), "=l"(hy[i]) : "r"(a));
                    s += (unsigned)(hx[i] >> 32) + (unsigned)(hy[i] >> 32);
                }
                if (s == tgt) break;
            }
#pragma unroll
            for (int i = 0; i < 8; i++) {
                float v0 = __uint_as_float((unsigned)hx[i]);
                float v1 = __uint_as_float((unsigned)hy[i]);
                unsigned long long hp2;
                asm("mov.b64 %0, {%1,%2};" : "=l"(hp2) : "f"(v0), "f"(v1));
                fma_f32x2(acc2, wp2[c * 8 + i], hp2);
            }
        }
        float lo, hi;
        asm("mov.b64 {%0,%1}, %2;" : "=f"(lo), "=f"(hi) : "l"(acc2));
        float acc = lo + hi;
        acc += __shfl_xor_sync(0xffffffffu, acc, 1);
        acc += __shfl_xor_sync(0xffffffffu, acc, 2);
        if (q == 0) ghs[rloc] = acc;
        __syncthreads();   // also guarantees all reads of hb64[cur] are done

        if (tid < 32) {   // warp 0: gates + output + publish h_new
            int o = rank * 32 + tid;
            float ghr = ghs[tid]      + bhh_s[tid];
            float ghz = ghs[32 + tid] + bhh_s[32 + tid];
            float ghn = ghs[64 + tid] + bhh_s[64 + tid];
            float r = fast_sigmoid(gir + ghr);
            float z = fast_sigmoid(giz + ghz);
            float n = fast_tanh(gin + r * ghn);
            float hold = __uint_as_float((unsigned)hb64[cur][(o >> 6) * 66 + (o & 63)]);
            float hnew = (1.f - z) * n + z * hold;
            out[((long)p * B_DIM + b) * O_DIM + o] = hnew;

            if (p < P_DIM - 1) {
                unsigned long long pv =
                    (((unsigned long long)(unsigned)(p + 1)) << 32) |
                    (unsigned long long)__float_as_uint(hnew);
                unsigned laddr = smem_u32(&hb64[nxt][(o >> 6) * 66 + (o & 63)]);
#pragma unroll
                for (int c2 = 0; c2 < 8; c2++) {
                    unsigned raddr;
                    asm("mapa.shared::cluster.u32 %0, %1, %2;" : "=r"(raddr) : "r"(laddr), "r"(c2));
                    asm volatile("st.relaxed.cluster.shared::cluster.u64 [%0], %1;"
                                 :: "r"(raddr), "l"(pv) : "memory");
                }
            }
        }
    }
}

// ---------------- launch ----------------
extern "C" void kernel_launch(void* const* d_in, const int* in_sizes, int n_in,
                              void* d_out, int out_size)
{
    const float* passage  = (const float*)d_in[0];
    const float* question = (const float*)d_in[1];
    const float* Wuq      = (const float*)d_in[2];
    const float* Wup      = (const float*)d_in[3];
    const float* v        = (const float*)d_in[4];
    const float* Wg       = (const float*)d_in[5];
    const float* w_ih     = (const float*)d_in[6];
    const float* w_hh     = (const float*)d_in[7];
    const float* b_ih     = (const float*)d_in[8];
    const float* b_hh     = (const float*)d_in[9];
    float* out = (float*)d_out;

    void *pWp, *pWq, *pGcat, *pCg, *pGi;
    cudaGetSymbolAddress(&pWp, g_Wp);
    cudaGetSymbolAddress(&pWq, g_Wq);
    cudaGetSymbolAddress(&pGcat, g_gcat);
    cudaGetSymbolAddress(&pCg, g_cg);
    cudaGetSymbolAddress(&pGi, g_gi);

    dim3 blk(256);

    gemm_kernel<0><<<dim3(8192 / 64, 256 / 64), blk>>>(
        passage, Wup, nullptr, nullptr, (float*)pWp, 8192, 256, 256);
    gemm_kernel<0><<<dim3(1024 / 64, 256 / 64), blk>>>(
        question, Wuq, nullptr, nullptr, (float*)pWq, 1024, 256, 256);
    attn_kernel<<<dim3(P_DIM, B_DIM), blk>>>(question, passage, v);
    gemm_kernel<2><<<dim3(8192 / 64, 256 / 64), blk>>>(
        (const float*)pGcat, Wg + 256 * 512, nullptr, (const float*)pGcat,
        (float*)pCg, 8192, 256, 512);
    gemm_kernel<1><<<dim3(8192 / 64, 768 / 64), blk>>>(
        (const float*)pCg, w_ih, b_ih, nullptr, (float*)pGi, 8192, 768, 256);
    gru_kernel<<<128, 384>>>((const float*)pGi, w_hh, b_hh, out);
}